// round 4
// baseline (speedup 1.0000x reference)
#include <cuda_runtime.h>
#include <math.h>

#define Bb 64
#define Ss 64
#define Tt 15
#define Hh 1024
#define Vv 50257

#define LP_OFF 0
#define HT_OFF (Bb*Tt*Vv)           // 48246720
#define AT_OFF (HT_OFF + Bb*Hh)     // 48312256

// ---------------- scratch (device globals; no allocs allowed) ----------------
__device__ float g_Uk[Bb*Ss*Hh];        // [b*S+s][k]  16 MB
__device__ float g_h[Bb*Hh];            // current hidden
__device__ float g_w[Bb*Ss];            // attention weights for current step
__device__ float g_x[Bb*2*Hh];          // [e | ctx]
__device__ float g_Hall[Bb*Tt*Hh];      // [(b*T+t)][h] — matches log_probs row order
__device__ float g_Pq [4*Bb*Hh];        // split-K partials for q
__device__ float g_Pgi[8*Bb*3*Hh];      // split-K partials for gi
__device__ float g_Pgh[4*Bb*3*Hh];      // split-K partials for gh

// ---------------- init: h = encoder_hidden[0] ----------------
__global__ void init_h_kernel(const float* __restrict__ ench) {
    int i = blockIdx.x * 1024 + threadIdx.x;
    g_h[i] = ench[i];
}

__global__ void copy_hT_kernel(float* __restrict__ out) {
    int i = blockIdx.x * 1024 + threadIdx.x;
    out[i] = g_h[i];
}

// ---------------- generic NT GEMM: C[m,n] = bias[n] + sum_k A[m,k]*B[n,k] ----
// BM=64, BN=128, BK=16, 256 threads, 4x8 per-thread tile. M multiple of 64,
// K multiple of 16; only N needs guards.
__global__ __launch_bounds__(256) void gemm64x128(
    const float* __restrict__ A, const float* __restrict__ Bm,
    const float* __restrict__ bias, float* __restrict__ C,
    int N, int K, int ldc)
{
    __shared__ float As[16][64];
    __shared__ float Bs[16][128];
    const int tid   = threadIdx.x;
    const int mBase = blockIdx.y * 64;
    const int nBase = blockIdx.x * 128;
    const int lrow  = tid >> 2;          // 0..63
    const int lk    = (tid & 3) * 4;     // 0,4,8,12
    const int ty    = tid >> 4;          // 0..15
    const int tx    = tid & 15;          // 0..15

    float acc[4][8];
#pragma unroll
    for (int i = 0; i < 4; i++)
#pragma unroll
        for (int j = 0; j < 8; j++) acc[i][j] = 0.f;

    for (int k0 = 0; k0 < K; k0 += 16) {
        float4 av = *reinterpret_cast<const float4*>(
            A + (size_t)(mBase + lrow) * K + k0 + lk);
        As[lk+0][lrow] = av.x; As[lk+1][lrow] = av.y;
        As[lk+2][lrow] = av.z; As[lk+3][lrow] = av.w;
#pragma unroll
        for (int r = 0; r < 2; r++) {
            int n = nBase + lrow + r * 64;
            float4 bv = make_float4(0.f, 0.f, 0.f, 0.f);
            if (n < N)
                bv = *reinterpret_cast<const float4*>(Bm + (size_t)n * K + k0 + lk);
            Bs[lk+0][lrow + r*64] = bv.x; Bs[lk+1][lrow + r*64] = bv.y;
            Bs[lk+2][lrow + r*64] = bv.z; Bs[lk+3][lrow + r*64] = bv.w;
        }
        __syncthreads();
#pragma unroll
        for (int kk = 0; kk < 16; kk++) {
            float4 a  = *reinterpret_cast<const float4*>(&As[kk][ty*4]);
            float4 b0 = *reinterpret_cast<const float4*>(&Bs[kk][tx*8]);
            float4 b1 = *reinterpret_cast<const float4*>(&Bs[kk][tx*8+4]);
            float ar[4] = {a.x, a.y, a.z, a.w};
            float br[8] = {b0.x, b0.y, b0.z, b0.w, b1.x, b1.y, b1.z, b1.w};
#pragma unroll
            for (int i = 0; i < 4; i++)
#pragma unroll
                for (int j = 0; j < 8; j++)
                    acc[i][j] = fmaf(ar[i], br[j], acc[i][j]);
        }
        __syncthreads();
    }
#pragma unroll
    for (int i = 0; i < 4; i++) {
        int m = mBase + ty*4 + i;
#pragma unroll
        for (int j = 0; j < 8; j++) {
            int n = nBase + tx*8 + j;
            if (n < N) C[(size_t)m * ldc + n] = acc[i][j] + bias[n];
        }
    }
}

// ---------------- skinny split-K GEMM: M=64 fixed ----------------
// grid (N/32, KS). Writes partials Cpart[(ks*64+m)*N + n] (no bias).
template <int KS>
__global__ __launch_bounds__(256) void gemm_skinny(
    const float* __restrict__ A, const float* __restrict__ Bm,
    float* __restrict__ Cpart, int N, int K)
{
    __shared__ float As[16][64];
    __shared__ float Bs[16][32];
    const int tid    = threadIdx.x;
    const int nBase  = blockIdx.x * 32;
    const int ks     = blockIdx.y;
    const int kchunk = K / KS;              // multiple of 16 by construction
    const int kStart = ks * kchunk;
    const int lrow   = tid >> 2;
    const int lk     = (tid & 3) * 4;
    const int ty     = tid >> 4;
    const int tx     = tid & 15;

    float acc[4][2] = {{0.f,0.f},{0.f,0.f},{0.f,0.f},{0.f,0.f}};

    for (int k0 = kStart; k0 < kStart + kchunk; k0 += 16) {
        float4 av = *reinterpret_cast<const float4*>(A + (size_t)lrow * K + k0 + lk);
        As[lk+0][lrow] = av.x; As[lk+1][lrow] = av.y;
        As[lk+2][lrow] = av.z; As[lk+3][lrow] = av.w;
        if (tid < 128) {
            int brow = tid >> 2;            // 0..31
            int bk   = (tid & 3) * 4;
            float4 bv = *reinterpret_cast<const float4*>(
                Bm + (size_t)(nBase + brow) * K + k0 + bk);
            Bs[bk+0][brow] = bv.x; Bs[bk+1][brow] = bv.y;
            Bs[bk+2][brow] = bv.z; Bs[bk+3][brow] = bv.w;
        }
        __syncthreads();
#pragma unroll
        for (int kk = 0; kk < 16; kk++) {
            float4 a = *reinterpret_cast<const float4*>(&As[kk][ty*4]);
            float2 b = *reinterpret_cast<const float2*>(&Bs[kk][tx*2]);
            acc[0][0] = fmaf(a.x, b.x, acc[0][0]);
            acc[0][1] = fmaf(a.x, b.y, acc[0][1]);
            acc[1][0] = fmaf(a.y, b.x, acc[1][0]);
            acc[1][1] = fmaf(a.y, b.y, acc[1][1]);
            acc[2][0] = fmaf(a.z, b.x, acc[2][0]);
            acc[2][1] = fmaf(a.z, b.y, acc[2][1]);
            acc[3][0] = fmaf(a.w, b.x, acc[3][0]);
            acc[3][1] = fmaf(a.w, b.y, acc[3][1]);
        }
        __syncthreads();
    }
#pragma unroll
    for (int i = 0; i < 4; i++)
#pragma unroll
        for (int j = 0; j < 2; j++)
            Cpart[(size_t)(ks*64 + ty*4 + i) * N + nBase + tx*2 + j] = acc[i][j];
}

// ---------------- attention scores + softmax (one block per b) ----------------
// q[b,k] = ba[k] + sum_ks Pq; scores[b,s] = sum_k tanh(q+Uk)*Va[k]; softmax over s.
// (bv shifts all scores equally -> no effect on softmax; skipped, mathematically exact.)
__global__ __launch_bounds__(256) void attn_scores_kernel(
    const float* __restrict__ Va, const float* __restrict__ ba,
    float* __restrict__ attn_out, int t)
{
    const int b   = blockIdx.x;
    const int tid = threadIdx.x;
    __shared__ float qsh[Hh];
    __shared__ float sc[Ss];

    for (int k = tid; k < Hh; k += 256) {
        float v = ba[k];
#pragma unroll
        for (int p = 0; p < 4; p++) v += g_Pq[(size_t)(p*Bb + b)*Hh + k];
        qsh[k] = v;
    }
    __syncthreads();

    const int warp = tid >> 5, lane = tid & 31;
    for (int s = warp; s < Ss; s += 8) {
        const float* uk = &g_Uk[(size_t)(b*Ss + s) * Hh];
        float acc = 0.f;
        for (int k = lane; k < Hh; k += 32)
            acc += tanhf(qsh[k] + uk[k]) * Va[k];
#pragma unroll
        for (int o = 16; o > 0; o >>= 1)
            acc += __shfl_xor_sync(0xffffffffu, acc, o);
        if (lane == 0) sc[s] = acc;
    }
    __syncthreads();

    if (tid < 32) {
        float x0 = sc[tid], x1 = sc[tid + 32];
        float m = fmaxf(x0, x1);
#pragma unroll
        for (int o = 16; o > 0; o >>= 1)
            m = fmaxf(m, __shfl_xor_sync(0xffffffffu, m, o));
        float e0 = expf(x0 - m), e1 = expf(x1 - m);
        float sum = e0 + e1;
#pragma unroll
        for (int o = 16; o > 0; o >>= 1)
            sum += __shfl_xor_sync(0xffffffffu, sum, o);
        float inv = 1.f / sum;
        float w0 = e0 * inv, w1 = e1 * inv;
        g_w[b*Ss + tid]      = w0;
        g_w[b*Ss + tid + 32] = w1;
        size_t ob = (size_t)(b*Tt + t) * Ss;
        attn_out[ob + tid]      = w0;
        attn_out[ob + tid + 32] = w1;
    }
}

// ---------------- context + embedding gather -> x = [e | ctx] ----------------
__global__ __launch_bounds__(256) void ctx_x_kernel(
    const float* __restrict__ enc, const float* __restrict__ emb,
    const int* __restrict__ target, int t)
{
    const int b = blockIdx.x;
    const int h = blockIdx.y * 256 + threadIdx.x;
    __shared__ float wsh[Ss];
    if (threadIdx.x < Ss) wsh[threadIdx.x] = g_w[b*Ss + threadIdx.x];
    __syncthreads();

    float acc = 0.f;
    const float* eb = enc + (size_t)(b*Ss) * Hh + h;
#pragma unroll
    for (int s = 0; s < Ss; s++) acc = fmaf(wsh[s], eb[(size_t)s * Hh], acc);
    g_x[(size_t)b*2*Hh + Hh + h] = acc;

    int tok = (t == 0) ? 0 : target[b*Tt + (t-1)];
    g_x[(size_t)b*2*Hh + h] = emb[(size_t)tok * Hh + h];
}

// ---------------- GRU combine: sum split-K partials + biases, update h --------
__global__ __launch_bounds__(256) void gru_combine_kernel(
    const float* __restrict__ b_ih, const float* __restrict__ b_hh, int t)
{
    const int idx = blockIdx.x * 256 + threadIdx.x;   // 0..65535
    const int b = idx >> 10;
    const int i = idx & 1023;

    float gir = b_ih[i], giz = b_ih[Hh + i], gin = b_ih[2*Hh + i];
#pragma unroll
    for (int p = 0; p < 8; p++) {
        const float* base = &g_Pgi[(size_t)(p*Bb + b) * 3 * Hh];
        gir += base[i]; giz += base[Hh + i]; gin += base[2*Hh + i];
    }
    float ghr = b_hh[i], ghz = b_hh[Hh + i], ghn = b_hh[2*Hh + i];
#pragma unroll
    for (int p = 0; p < 4; p++) {
        const float* base = &g_Pgh[(size_t)(p*Bb + b) * 3 * Hh];
        ghr += base[i]; ghz += base[Hh + i]; ghn += base[2*Hh + i];
    }
    float r = 1.f / (1.f + expf(-(gir + ghr)));
    float z = 1.f / (1.f + expf(-(giz + ghz)));
    float n = tanhf(gin + r * ghn);
    float hprev = g_h[idx];
    float hnew  = (1.f - z) * n + z * hprev;
    g_h[idx] = hnew;
    g_Hall[(size_t)(b*Tt + t) * Hh + i] = hnew;
}

// ---------------- in-place log_softmax over V per row ----------------
__global__ __launch_bounds__(256) void log_softmax_kernel(float* __restrict__ out)
{
    const int row = blockIdx.x;                      // b*T + t
    float* x = out + (size_t)row * Vv;
    const int tid = threadIdx.x;

    float m = -INFINITY, s = 0.f;
    for (int v = tid; v < Vv; v += 256) {
        float xv = x[v];
        if (xv > m) { s = s * expf(m - xv) + 1.f; m = xv; }
        else        { s += expf(xv - m); }
    }
    __shared__ float sm[256], ss[256];
    sm[tid] = m; ss[tid] = s;
    __syncthreads();
    for (int stride = 128; stride > 0; stride >>= 1) {
        if (tid < stride) {
            float m2 = sm[tid + stride], s2 = ss[tid + stride];
            float M = fmaxf(sm[tid], m2);
            ss[tid] = ss[tid] * expf(sm[tid] - M) + s2 * expf(m2 - M);
            sm[tid] = M;
        }
        __syncthreads();
    }
    float lse = sm[0] + logf(ss[0]);
    for (int v = tid; v < Vv; v += 256) x[v] = x[v] - lse;
}

// ---------------- launch ----------------
extern "C" void kernel_launch(void* const* d_in, const int* in_sizes, int n_in,
                              void* d_out, int out_size)
{
    const float* enc   = (const float*)d_in[0];   // [B,S,H]
    const float* ench  = (const float*)d_in[1];   // [1,B,H]
    const int*   target= (const int*)  d_in[2];   // [B,T]
    const float* emb   = (const float*)d_in[3];   // [V,H]
    const float* Wa    = (const float*)d_in[4];   // [H,H]
    const float* ba    = (const float*)d_in[5];   // [H]
    const float* Ua    = (const float*)d_in[6];   // [H,H]
    const float* bu    = (const float*)d_in[7];   // [H]
    const float* Va    = (const float*)d_in[8];   // [1,H]
    /* bv = d_in[9]: uniform shift before softmax -> no effect, skipped */
    const float* W_ih  = (const float*)d_in[10];  // [3H,2H]
    const float* W_hh  = (const float*)d_in[11];  // [3H,H]
    const float* b_ih  = (const float*)d_in[12];  // [3H]
    const float* b_hh  = (const float*)d_in[13];  // [3H]
    const float* Wout  = (const float*)d_in[14];  // [V,H]
    const float* bout  = (const float*)d_in[15];  // [V]

    float* out = (float*)d_out;
    float* lp  = out + LP_OFF;
    float* hT  = out + HT_OFF;
    float* at  = out + AT_OFF;

    float *pUk, *pH, *pX, *pHall, *pPq, *pPgi, *pPgh;
    cudaGetSymbolAddress((void**)&pUk,   g_Uk);
    cudaGetSymbolAddress((void**)&pH,    g_h);
    cudaGetSymbolAddress((void**)&pX,    g_x);
    cudaGetSymbolAddress((void**)&pHall, g_Hall);
    cudaGetSymbolAddress((void**)&pPq,   g_Pq);
    cudaGetSymbolAddress((void**)&pPgi,  g_Pgi);
    cudaGetSymbolAddress((void**)&pPgh,  g_Pgh);

    // h0 = encoder_hidden[0]
    init_h_kernel<<<Bb, 1024>>>(ench);

    // Uk = enc @ Ua.T + bu   : M=4096, N=1024, K=1024
    gemm64x128<<<dim3(Hh/128, (Bb*Ss)/64), 256>>>(enc, Ua, bu, pUk, Hh, Hh, Hh);

    for (int t = 0; t < Tt; t++) {
        // q = h @ Wa.T (+ba in scores kernel) : split-K=4
        gemm_skinny<4><<<dim3(Hh/32, 4), 256>>>(pH, Wa, pPq, Hh, Hh);
        attn_scores_kernel<<<Bb, 256>>>(Va, ba, at, t);
        ctx_x_kernel<<<dim3(Bb, Hh/256), 256>>>(enc, emb, target, t);
        // gi = x @ W_ih.T : K=2048, split-K=8 ; gh = h @ W_hh.T : K=1024, split-K=4
        gemm_skinny<8><<<dim3(3*Hh/32, 8), 256>>>(pX, W_ih, pPgi, 3*Hh, 2*Hh);
        gemm_skinny<4><<<dim3(3*Hh/32, 4), 256>>>(pH, W_hh, pPgh, 3*Hh, Hh);
        gru_combine_kernel<<<(Bb*Hh)/256, 256>>>(b_ih, b_hh, t);
    }

    // logits (all steps batched): Hall[960,1024] @ Wout.T + bout -> lp rows b*T+t
    gemm64x128<<<dim3((Vv + 127)/128, (Bb*Tt)/64), 256>>>(pHall, Wout, bout, lp, Vv, Hh, Vv);

    // in-place log_softmax over V
    log_softmax_kernel<<<Bb*Tt, 256>>>(lp);

    // hT output
    copy_hT_kernel<<<Bb, 1024>>>(hT);
}

// round 7
// speedup vs baseline: 2.2374x; 2.2374x over previous
#include <cuda_runtime.h>
#include <cuda_bf16.h>
#include <cstdint>
#include <stdint.h>
#include <math.h>

#define Bb 64
#define Ss 64
#define Tt 15
#define Hh 1024
#define Vv 50257

#define LP_OFF 0
#define HT_OFF (Bb*Tt*Vv)           // 48246720
#define AT_OFF (HT_OFF + Bb*Hh)     // 48312256

// ---------------- scratch (device globals; no allocs allowed) ----------------
__device__ float g_Uk[Bb*Ss*Hh];        // [b*S+s][k]  16 MB
__device__ float g_h[Bb*Hh];            // current hidden
__device__ float g_sc[Bb*Ss];           // attention scores (pre-softmax)
__device__ float g_x[Bb*2*Hh];          // [e | ctx]
__device__ float g_Hall[Bb*Tt*Hh];      // [(b*T+t)][h]
__device__ float g_Pq [4*Bb*Hh];        // split-K partials for q
__device__ float g_Pgi[8*Bb*3*Hh];      // split-K partials for gi
__device__ float g_Pgh[4*Bb*3*Hh];      // split-K partials for gh
__device__ __nv_bfloat16 g_WoutB[(size_t)Vv*Hh];   // 103 MB bf16 Wout
__device__ __nv_bfloat16 g_HallB[Bb*Tt*Hh];        // 2 MB bf16 Hall

// ---------------- ldmatrix / mma helpers (scalar-ref asm operands) ----------
__device__ __forceinline__ void ldsm_x4(unsigned int& r0, unsigned int& r1,
                                        unsigned int& r2, unsigned int& r3,
                                        const void* p)
{
    unsigned int addr = (unsigned int)__cvta_generic_to_shared(p);
    asm volatile("ldmatrix.sync.aligned.m8n8.x4.shared.b16 {%0,%1,%2,%3}, [%4];"
        : "=r"(r0), "=r"(r1), "=r"(r2), "=r"(r3) : "r"(addr));
}

__device__ __forceinline__ void mma_bf16_16816(float& c0, float& c1,
                                               float& c2, float& c3,
                                               unsigned int a0, unsigned int a1,
                                               unsigned int a2, unsigned int a3,
                                               unsigned int b0, unsigned int b1)
{
    asm volatile(
        "mma.sync.aligned.m16n8k16.row.col.f32.bf16.bf16.f32 "
        "{%0,%1,%2,%3}, {%4,%5,%6,%7}, {%8,%9}, {%0,%1,%2,%3};"
        : "+f"(c0), "+f"(c1), "+f"(c2), "+f"(c3)
        : "r"(a0), "r"(a1), "r"(a2), "r"(a3), "r"(b0), "r"(b1));
}

// ---------------- small helpers ----------------
__global__ void init_h_kernel(const float* __restrict__ ench) {
    int i = blockIdx.x * 1024 + threadIdx.x;
    g_h[i] = ench[i];
}
__global__ void copy_hT_kernel(float* __restrict__ out) {
    int i = blockIdx.x * 1024 + threadIdx.x;
    out[i] = g_h[i];
}

// fp32 -> bf16 conversion, 4 elems/thread (n multiple of 4)
__global__ __launch_bounds__(256) void f32_to_bf16_kernel(
    const float* __restrict__ in, __nv_bfloat16* __restrict__ out, int n4)
{
    int i = blockIdx.x * 256 + threadIdx.x;
    if (i >= n4) return;
    float4 v = reinterpret_cast<const float4*>(in)[i];
    __nv_bfloat162 lo = __float22bfloat162_rn(make_float2(v.x, v.y));
    __nv_bfloat162 hi = __float22bfloat162_rn(make_float2(v.z, v.w));
    reinterpret_cast<__nv_bfloat162*>(out)[i*2]   = lo;
    reinterpret_cast<__nv_bfloat162*>(out)[i*2+1] = hi;
}

// ---------------- bf16 tensor-core GEMM: C = A @ B^T + bias ----------------
// A: [M,K] bf16, B: [N,K] bf16 (K contiguous both), C fp32 [M,ldc].
// BM=64, BN=64, BK=32, 128 threads (4 warps, 2x2), warp tile 32x32.
// M multiple of 64; N guarded. grid = (M/64, ceil(N/64)) — M-fastest for B L2 reuse.
#define MMA_PAD 8
__global__ __launch_bounds__(128) void gemm_mma_bf16(
    const __nv_bfloat16* __restrict__ A, const __nv_bfloat16* __restrict__ Bm,
    const float* __restrict__ bias, float* __restrict__ C,
    int M, int N, int K, int ldc)
{
    __shared__ __nv_bfloat16 As[64][32 + MMA_PAD];
    __shared__ __nv_bfloat16 Bs[64][32 + MMA_PAD];
    const int tid   = threadIdx.x;
    const int lane  = tid & 31;
    const int warp  = tid >> 5;
    const int warpM = warp & 1;          // 0..1
    const int warpN = warp >> 1;         // 0..1
    const int mBase = blockIdx.x * 64;
    const int nBase = blockIdx.y * 64;

    float acc[2][4][4];
#pragma unroll
    for (int i = 0; i < 2; i++)
#pragma unroll
        for (int j = 0; j < 4; j++)
#pragma unroll
            for (int e = 0; e < 4; e++) acc[i][j][e] = 0.f;

    // load mapping: 64 rows x 32 bf16; 2x 16B chunks per thread, same row
    const int lr0 = tid >> 1;            // row 0..63
    const int lq0 = (tid & 1) * 16;      // bf16 col offset 0 or 16

    for (int k0 = 0; k0 < K; k0 += 32) {
        // A tile
        {
            const __nv_bfloat16* src = A + (size_t)(mBase + lr0) * K + k0 + lq0;
            uint4 v0 = *reinterpret_cast<const uint4*>(src);
            uint4 v1 = *reinterpret_cast<const uint4*>(src + 8);
            *reinterpret_cast<uint4*>(&As[lr0][lq0])     = v0;
            *reinterpret_cast<uint4*>(&As[lr0][lq0 + 8]) = v1;
        }
        // B tile (guard rows >= N)
        {
            int n = nBase + lr0;
            uint4 v0 = make_uint4(0u,0u,0u,0u);
            uint4 v1 = make_uint4(0u,0u,0u,0u);
            if (n < N) {
                const __nv_bfloat16* src = Bm + (size_t)n * K + k0 + lq0;
                v0 = *reinterpret_cast<const uint4*>(src);
                v1 = *reinterpret_cast<const uint4*>(src + 8);
            }
            *reinterpret_cast<uint4*>(&Bs[lr0][lq0])     = v0;
            *reinterpret_cast<uint4*>(&Bs[lr0][lq0 + 8]) = v1;
        }
        __syncthreads();

#pragma unroll
        for (int k16 = 0; k16 < 32; k16 += 16) {
            unsigned int afrag[2][4];
#pragma unroll
            for (int ti = 0; ti < 2; ti++) {
                int arow = warpM * 32 + ti * 16 + (lane & 15);
                int acol = k16 + (lane >> 4) * 8;
                ldsm_x4(afrag[ti][0], afrag[ti][1], afrag[ti][2], afrag[ti][3],
                        &As[arow][acol]);
            }
            unsigned int bfrag[4][2];
#pragma unroll
            for (int tj = 0; tj < 2; tj++) {
                int grp  = lane >> 3;
                int brow = warpN * 32 + tj * 16 + (lane & 7) + ((grp >> 1) << 3);
                int bcol = k16 + ((grp & 1) << 3);
                unsigned int q0, q1, q2, q3;
                ldsm_x4(q0, q1, q2, q3, &Bs[brow][bcol]);
                bfrag[tj*2][0]   = q0; bfrag[tj*2][1]   = q1;
                bfrag[tj*2+1][0] = q2; bfrag[tj*2+1][1] = q3;
            }
#pragma unroll
            for (int ti = 0; ti < 2; ti++)
#pragma unroll
                for (int nj = 0; nj < 4; nj++)
                    mma_bf16_16816(acc[ti][nj][0], acc[ti][nj][1],
                                   acc[ti][nj][2], acc[ti][nj][3],
                                   afrag[ti][0], afrag[ti][1],
                                   afrag[ti][2], afrag[ti][3],
                                   bfrag[nj][0], bfrag[nj][1]);
        }
        __syncthreads();
    }

    // epilogue
#pragma unroll
    for (int ti = 0; ti < 2; ti++) {
        int m0 = mBase + warpM * 32 + ti * 16 + (lane >> 2);
#pragma unroll
        for (int nj = 0; nj < 4; nj++) {
            int n = nBase + warpN * 32 + nj * 8 + (lane & 3) * 2;
            if (n < N) {
                C[(size_t)m0 * ldc + n]     = acc[ti][nj][0] + bias[n];
                C[(size_t)(m0+8) * ldc + n] = acc[ti][nj][2] + bias[n];
            }
            if (n + 1 < N) {
                C[(size_t)m0 * ldc + n + 1]     = acc[ti][nj][1] + bias[n+1];
                C[(size_t)(m0+8) * ldc + n + 1] = acc[ti][nj][3] + bias[n+1];
            }
        }
    }
}

// ---------------- fp32 NT GEMM (Uk precompute): C = A@B^T + bias ------------
__global__ __launch_bounds__(256) void gemm64x128(
    const float* __restrict__ A, const float* __restrict__ Bm,
    const float* __restrict__ bias, float* __restrict__ C,
    int N, int K, int ldc)
{
    __shared__ float As[16][64];
    __shared__ float Bs[16][128];
    const int tid   = threadIdx.x;
    const int mBase = blockIdx.y * 64;
    const int nBase = blockIdx.x * 128;
    const int lrow  = tid >> 2;
    const int lk    = (tid & 3) * 4;
    const int ty    = tid >> 4;
    const int tx    = tid & 15;

    float acc[4][8];
#pragma unroll
    for (int i = 0; i < 4; i++)
#pragma unroll
        for (int j = 0; j < 8; j++) acc[i][j] = 0.f;

    for (int k0 = 0; k0 < K; k0 += 16) {
        float4 av = *reinterpret_cast<const float4*>(
            A + (size_t)(mBase + lrow) * K + k0 + lk);
        As[lk+0][lrow] = av.x; As[lk+1][lrow] = av.y;
        As[lk+2][lrow] = av.z; As[lk+3][lrow] = av.w;
#pragma unroll
        for (int r = 0; r < 2; r++) {
            int n = nBase + lrow + r * 64;
            float4 bv = make_float4(0.f, 0.f, 0.f, 0.f);
            if (n < N)
                bv = *reinterpret_cast<const float4*>(Bm + (size_t)n * K + k0 + lk);
            Bs[lk+0][lrow + r*64] = bv.x; Bs[lk+1][lrow + r*64] = bv.y;
            Bs[lk+2][lrow + r*64] = bv.z; Bs[lk+3][lrow + r*64] = bv.w;
        }
        __syncthreads();
#pragma unroll
        for (int kk = 0; kk < 16; kk++) {
            float4 a  = *reinterpret_cast<const float4*>(&As[kk][ty*4]);
            float4 b0 = *reinterpret_cast<const float4*>(&Bs[kk][tx*8]);
            float4 b1 = *reinterpret_cast<const float4*>(&Bs[kk][tx*8+4]);
            float ar[4] = {a.x, a.y, a.z, a.w};
            float br[8] = {b0.x, b0.y, b0.z, b0.w, b1.x, b1.y, b1.z, b1.w};
#pragma unroll
            for (int i = 0; i < 4; i++)
#pragma unroll
                for (int j = 0; j < 8; j++)
                    acc[i][j] = fmaf(ar[i], br[j], acc[i][j]);
        }
        __syncthreads();
    }
#pragma unroll
    for (int i = 0; i < 4; i++) {
        int m = mBase + ty*4 + i;
#pragma unroll
        for (int j = 0; j < 8; j++) {
            int n = nBase + tx*8 + j;
            if (n < N) C[(size_t)m * ldc + n] = acc[i][j] + bias[n];
        }
    }
}

// ---------------- skinny split-K GEMM: M=64, 64-wide N tiles ----------------
// grid (N/64, KS). Cpart[(ks*64+m)*N + n], no bias.
template <int KS>
__global__ __launch_bounds__(256) void gemm_skinny(
    const float* __restrict__ A, const float* __restrict__ Bm,
    float* __restrict__ Cpart, int N, int K)
{
    __shared__ float As[16][64];
    __shared__ float Bs[16][64];
    const int tid    = threadIdx.x;
    const int nBase  = blockIdx.x * 64;
    const int ks     = blockIdx.y;
    const int kchunk = K / KS;
    const int kStart = ks * kchunk;
    const int lrow   = tid >> 2;
    const int lk     = (tid & 3) * 4;
    const int ty     = tid >> 4;
    const int tx     = tid & 15;

    float acc[4][4];
#pragma unroll
    for (int i = 0; i < 4; i++)
#pragma unroll
        for (int j = 0; j < 4; j++) acc[i][j] = 0.f;

    for (int k0 = kStart; k0 < kStart + kchunk; k0 += 16) {
        float4 av = *reinterpret_cast<const float4*>(A + (size_t)lrow * K + k0 + lk);
        As[lk+0][lrow] = av.x; As[lk+1][lrow] = av.y;
        As[lk+2][lrow] = av.z; As[lk+3][lrow] = av.w;
        float4 bv = *reinterpret_cast<const float4*>(
            Bm + (size_t)(nBase + lrow) * K + k0 + lk);
        Bs[lk+0][lrow] = bv.x; Bs[lk+1][lrow] = bv.y;
        Bs[lk+2][lrow] = bv.z; Bs[lk+3][lrow] = bv.w;
        __syncthreads();
#pragma unroll
        for (int kk = 0; kk < 16; kk++) {
            float4 a = *reinterpret_cast<const float4*>(&As[kk][ty*4]);
            float4 b = *reinterpret_cast<const float4*>(&Bs[kk][tx*4]);
            float ar[4] = {a.x, a.y, a.z, a.w};
            float br[4] = {b.x, b.y, b.z, b.w};
#pragma unroll
            for (int i = 0; i < 4; i++)
#pragma unroll
                for (int j = 0; j < 4; j++)
                    acc[i][j] = fmaf(ar[i], br[j], acc[i][j]);
        }
        __syncthreads();
    }
#pragma unroll
    for (int i = 0; i < 4; i++)
#pragma unroll
        for (int j = 0; j < 4; j++)
            Cpart[(size_t)(ks*64 + ty*4 + i) * N + nBase + tx*4 + j] = acc[i][j];
}

// ---------------- attention scores (one block per (b, 8 s-values)) ----------
__device__ __forceinline__ float tanh_fast(float x) {
    float y;
    asm("tanh.approx.f32 %0, %1;" : "=f"(y) : "f"(x));
    return y;
}

__global__ __launch_bounds__(256) void attn_scores_kernel(
    const float* __restrict__ Va, const float* __restrict__ ba)
{
    const int b   = blockIdx.x;
    const int tid = threadIdx.x;
    __shared__ float qsh[Hh];

    for (int k = tid; k < Hh; k += 256) {
        float v = ba[k];
#pragma unroll
        for (int p = 0; p < 4; p++) v += g_Pq[(size_t)(p*Bb + b)*Hh + k];
        qsh[k] = v;
    }
    __syncthreads();

    const int warp = tid >> 5, lane = tid & 31;
    const int s = blockIdx.y * 8 + warp;
    const float* uk = &g_Uk[(size_t)(b*Ss + s) * Hh];
    float acc = 0.f;
#pragma unroll 4
    for (int k = lane; k < Hh; k += 32)
        acc += tanh_fast(qsh[k] + uk[k]) * Va[k];
#pragma unroll
    for (int o = 16; o > 0; o >>= 1)
        acc += __shfl_xor_sync(0xffffffffu, acc, o);
    if (lane == 0) g_sc[b*Ss + s] = acc;
}

// ---------------- softmax + context + embedding gather -> x = [e | ctx] -----
__global__ __launch_bounds__(256) void ctx_x_kernel(
    const float* __restrict__ enc, const float* __restrict__ emb,
    const int* __restrict__ target, float* __restrict__ attn_out, int t)
{
    const int b = blockIdx.x;
    const int tid = threadIdx.x;
    __shared__ float wsh[Ss];
    if (tid < Ss) wsh[tid] = g_sc[b*Ss + tid];
    __syncthreads();
    if (tid < 32) {
        float x0 = wsh[tid], x1 = wsh[tid + 32];
        float m = fmaxf(x0, x1);
#pragma unroll
        for (int o = 16; o > 0; o >>= 1)
            m = fmaxf(m, __shfl_xor_sync(0xffffffffu, m, o));
        float e0 = expf(x0 - m), e1 = expf(x1 - m);
        float sum = e0 + e1;
#pragma unroll
        for (int o = 16; o > 0; o >>= 1)
            sum += __shfl_xor_sync(0xffffffffu, sum, o);
        float inv = 1.f / sum;
        float w0 = e0 * inv, w1 = e1 * inv;
        wsh[tid] = w0; wsh[tid + 32] = w1;
        if (blockIdx.y == 0) {
            size_t ob = (size_t)(b*Tt + t) * Ss;
            attn_out[ob + tid]      = w0;
            attn_out[ob + tid + 32] = w1;
        }
    }
    __syncthreads();

    const int h = blockIdx.y * 256 + tid;
    float acc = 0.f;
    const float* eb = enc + (size_t)(b*Ss) * Hh + h;
#pragma unroll
    for (int s = 0; s < Ss; s++) acc = fmaf(wsh[s], eb[(size_t)s * Hh], acc);
    g_x[(size_t)b*2*Hh + Hh + h] = acc;

    int tok = (t == 0) ? 0 : target[b*Tt + (t-1)];
    g_x[(size_t)b*2*Hh + h] = emb[(size_t)tok * Hh + h];
}

// ---------------- GRU combine --------------------------------------------
__global__ __launch_bounds__(256) void gru_combine_kernel(
    const float* __restrict__ b_ih, const float* __restrict__ b_hh, int t)
{
    const int idx = blockIdx.x * 256 + threadIdx.x;
    const int b = idx >> 10;
    const int i = idx & 1023;

    float gir = b_ih[i], giz = b_ih[Hh + i], gin = b_ih[2*Hh + i];
#pragma unroll
    for (int p = 0; p < 8; p++) {
        const float* base = &g_Pgi[(size_t)(p*Bb + b) * 3 * Hh];
        gir += base[i]; giz += base[Hh + i]; gin += base[2*Hh + i];
    }
    float ghr = b_hh[i], ghz = b_hh[Hh + i], ghn = b_hh[2*Hh + i];
#pragma unroll
    for (int p = 0; p < 4; p++) {
        const float* base = &g_Pgh[(size_t)(p*Bb + b) * 3 * Hh];
        ghr += base[i]; ghz += base[Hh + i]; ghn += base[2*Hh + i];
    }
    float r = 1.f / (1.f + expf(-(gir + ghr)));
    float z = 1.f / (1.f + expf(-(giz + ghz)));
    float n = tanhf(gin + r * ghn);
    float hprev = g_h[idx];
    float hnew  = (1.f - z) * n + z * hprev;
    g_h[idx] = hnew;
    g_Hall[(size_t)(b*Tt + t) * Hh + i] = hnew;
}

// ---------------- in-place log_softmax over V per row ----------------
__global__ __launch_bounds__(256) void log_softmax_kernel(float* __restrict__ out)
{
    const int row = blockIdx.x;
    float* x = out + (size_t)row * Vv;
    const int tid = threadIdx.x;

    float m = -INFINITY, s = 0.f;
    for (int v = tid; v < Vv; v += 256) {
        float xv = x[v];
        if (xv > m) { s = s * expf(m - xv) + 1.f; m = xv; }
        else        { s += expf(xv - m); }
    }
    __shared__ float sm[256], ss[256];
    sm[tid] = m; ss[tid] = s;
    __syncthreads();
    for (int stride = 128; stride > 0; stride >>= 1) {
        if (tid < stride) {
            float m2 = sm[tid + stride], s2 = ss[tid + stride];
            float M = fmaxf(sm[tid], m2);
            ss[tid] = ss[tid] * expf(sm[tid] - M) + s2 * expf(m2 - M);
            sm[tid] = M;
        }
        __syncthreads();
    }
    float lse = sm[0] + logf(ss[0]);
    for (int v = tid; v < Vv; v += 256) x[v] = x[v] - lse;
}

// ---------------- launch ----------------
extern "C" void kernel_launch(void* const* d_in, const int* in_sizes, int n_in,
                              void* d_out, int out_size)
{
    const float* enc   = (const float*)d_in[0];
    const float* ench  = (const float*)d_in[1];
    const int*   target= (const int*)  d_in[2];
    const float* emb   = (const float*)d_in[3];
    const float* Wa    = (const float*)d_in[4];
    const float* ba    = (const float*)d_in[5];
    const float* Ua    = (const float*)d_in[6];
    const float* bu    = (const float*)d_in[7];
    const float* Va    = (const float*)d_in[8];
    /* bv (d_in[9]): uniform shift before softmax — no effect */
    const float* W_ih  = (const float*)d_in[10];
    const float* W_hh  = (const float*)d_in[11];
    const float* b_ih  = (const float*)d_in[12];
    const float* b_hh  = (const float*)d_in[13];
    const float* Wout  = (const float*)d_in[14];
    const float* bout  = (const float*)d_in[15];

    float* out = (float*)d_out;
    float* lp  = out + LP_OFF;
    float* hT  = out + HT_OFF;
    float* at  = out + AT_OFF;

    float *pUk, *pH, *pX, *pHall, *pPq, *pPgi, *pPgh;
    __nv_bfloat16 *pWoutB, *pHallB;
    cudaGetSymbolAddress((void**)&pUk,    g_Uk);
    cudaGetSymbolAddress((void**)&pH,     g_h);
    cudaGetSymbolAddress((void**)&pX,     g_x);
    cudaGetSymbolAddress((void**)&pHall,  g_Hall);
    cudaGetSymbolAddress((void**)&pPq,    g_Pq);
    cudaGetSymbolAddress((void**)&pPgi,   g_Pgi);
    cudaGetSymbolAddress((void**)&pPgh,   g_Pgh);
    cudaGetSymbolAddress((void**)&pWoutB, g_WoutB);
    cudaGetSymbolAddress((void**)&pHallB, g_HallB);

    init_h_kernel<<<Bb, 1024>>>(ench);

    // Wout -> bf16 (independent of the recurrence)
    {
        int n4 = (Vv * Hh) / 4;   // 12,865,792
        f32_to_bf16_kernel<<<(n4 + 255)/256, 256>>>(Wout, pWoutB, n4);
    }

    // Uk = enc @ Ua.T + bu (fp32; feeds recurrence — keep precise)
    gemm64x128<<<dim3(Hh/128, (Bb*Ss)/64), 256>>>(enc, Ua, bu, pUk, Hh, Hh, Hh);

    for (int t = 0; t < Tt; t++) {
        gemm_skinny<4><<<dim3(Hh/64, 4), 256>>>(pH, Wa, pPq, Hh, Hh);
        attn_scores_kernel<<<dim3(Bb, Ss/8), 256>>>(Va, ba);
        ctx_x_kernel<<<dim3(Bb, Hh/256), 256>>>(enc, emb, target, at, t);
        gemm_skinny<8><<<dim3(3*Hh/64, 8), 256>>>(pX, W_ih, pPgi, 3*Hh, 2*Hh);
        gemm_skinny<4><<<dim3(3*Hh/64, 4), 256>>>(pH, W_hh, pPgh, 3*Hh, Hh);
        gru_combine_kernel<<<(Bb*Hh)/256, 256>>>(b_ih, b_hh, t);
    }

    // Hall -> bf16
    {
        int n4 = (Bb * Tt * Hh) / 4;
        f32_to_bf16_kernel<<<(n4 + 255)/256, 256>>>(pHall, pHallB, n4);
    }

    // logits: Hall_bf16[960,1024] @ WoutB^T + bout (tensor cores)
    gemm_mma_bf16<<<dim3((Bb*Tt)/64, (Vv + 63)/64), 128>>>(
        pHallB, pWoutB, bout, lp, Bb*Tt, Vv, Hh, Vv);

    log_softmax_kernel<<<Bb*Tt, 256>>>(lp);
    copy_hT_kernel<<<Bb, 1024>>>(hT);
}

// round 8
// speedup vs baseline: 3.1617x; 1.4131x over previous
#include <cuda_runtime.h>
#include <cuda_bf16.h>
#include <cstdint>
#include <stdint.h>
#include <math.h>

#define Bb 64
#define Ss 64
#define Tt 15
#define Hh 1024
#define Vv 50257

#define LP_OFF 0
#define HT_OFF (Bb*Tt*Vv)           // 48246720
#define AT_OFF (HT_OFF + Bb*Hh)     // 48312256

// ---------------- scratch (device globals; no allocs allowed) ----------------
__device__ float g_Uk[Bb*Ss*Hh];            // [b*S+s][k]  16 MB
__device__ float g_h[Bb*Hh];                // current hidden
__device__ float g_ctx[Bb*Hh];              // context vectors
__device__ float g_Hall[Bb*Tt*Hh];          // [(b*T+t)][h]
__device__ float g_E[Bb*Tt*Hh];             // gathered embeddings, row = t*B+b
__device__ float g_giE[(size_t)Bb*Tt*3*Hh]; // gi embedding part (+b_ih), row = t*B+b
__device__ float g_Whq[4*Hh*Hh];            // [Wa ; W_hh] fused  16 MB
__device__ float g_Phq[4*Bb*4*Hh];          // split-K partials: q | gh
__device__ float g_Pgc[4*Bb*3*Hh];          // split-K partials: gi ctx part
__device__ __nv_bfloat16 g_WoutB[(size_t)Vv*Hh];   // 103 MB bf16 Wout
__device__ __nv_bfloat16 g_HallB[Bb*Tt*Hh];        // 2 MB bf16 Hall

// ---------------- asm helpers ----------------
__device__ __forceinline__ float tanh_fast(float x) {
    float y;
    asm("tanh.approx.f32 %0, %1;" : "=f"(y) : "f"(x));
    return y;
}
__device__ __forceinline__ float cvt_tf32(float x) {
    unsigned u;
    asm("cvt.rna.tf32.f32 %0, %1;" : "=r"(u) : "f"(x));
    return __uint_as_float(u);
}
__device__ __forceinline__ void ldsm_x4(unsigned& r0, unsigned& r1,
                                        unsigned& r2, unsigned& r3,
                                        const void* p)
{
    unsigned addr = (unsigned)__cvta_generic_to_shared(p);
    asm volatile("ldmatrix.sync.aligned.m8n8.x4.shared.b16 {%0,%1,%2,%3}, [%4];"
        : "=r"(r0), "=r"(r1), "=r"(r2), "=r"(r3) : "r"(addr));
}
__device__ __forceinline__ void mma_bf16_16816(float& c0, float& c1,
                                               float& c2, float& c3,
                                               unsigned a0, unsigned a1,
                                               unsigned a2, unsigned a3,
                                               unsigned b0, unsigned b1)
{
    asm volatile(
        "mma.sync.aligned.m16n8k16.row.col.f32.bf16.bf16.f32 "
        "{%0,%1,%2,%3}, {%4,%5,%6,%7}, {%8,%9}, {%0,%1,%2,%3};"
        : "+f"(c0), "+f"(c1), "+f"(c2), "+f"(c3)
        : "r"(a0), "r"(a1), "r"(a2), "r"(a3), "r"(b0), "r"(b1));
}
__device__ __forceinline__ void mma_tf32_16808(float& c0, float& c1,
                                               float& c2, float& c3,
                                               unsigned a0, unsigned a1,
                                               unsigned a2, unsigned a3,
                                               unsigned b0, unsigned b1)
{
    asm volatile(
        "mma.sync.aligned.m16n8k8.row.col.f32.tf32.tf32.f32 "
        "{%0,%1,%2,%3}, {%4,%5,%6,%7}, {%8,%9}, {%0,%1,%2,%3};"
        : "+f"(c0), "+f"(c1), "+f"(c2), "+f"(c3)
        : "r"(a0), "r"(a1), "r"(a2), "r"(a3), "r"(b0), "r"(b1));
}

// ---------------- small prep kernels ----------------
__global__ void init_h_kernel(const float* __restrict__ ench) {
    int i = blockIdx.x * 1024 + threadIdx.x;
    g_h[i] = ench[i];
}
__global__ void copy_hT_kernel(float* __restrict__ out) {
    int i = blockIdx.x * 1024 + threadIdx.x;
    out[i] = g_h[i];
}
__global__ __launch_bounds__(256) void f32_to_bf16_kernel(
    const float* __restrict__ in, __nv_bfloat16* __restrict__ out, int n4)
{
    int i = blockIdx.x * 256 + threadIdx.x;
    if (i >= n4) return;
    float4 v = reinterpret_cast<const float4*>(in)[i];
    __nv_bfloat162 lo = __float22bfloat162_rn(make_float2(v.x, v.y));
    __nv_bfloat162 hi = __float22bfloat162_rn(make_float2(v.z, v.w));
    reinterpret_cast<__nv_bfloat162*>(out)[i*2]   = lo;
    reinterpret_cast<__nv_bfloat162*>(out)[i*2+1] = hi;
}
// Whq = [Wa (rows 0..1023) ; W_hh (rows 1024..4095)]
__global__ __launch_bounds__(256) void build_Whq_kernel(
    const float* __restrict__ Wa, const float* __restrict__ W_hh)
{
    int i4 = blockIdx.x * 256 + threadIdx.x;   // 4096*256 float4s
    int r  = i4 >> 8;
    int c  = i4 & 255;
    const float* src = (r < Hh) ? (Wa + (size_t)r * Hh)
                                : (W_hh + (size_t)(r - Hh) * Hh);
    reinterpret_cast<float4*>(&g_Whq[(size_t)r * Hh])[c] =
        reinterpret_cast<const float4*>(src)[c];
}
// E[t*B+b] = emb[inputs[b][t]]
__global__ __launch_bounds__(256) void gather_E_kernel(
    const float* __restrict__ emb, const int* __restrict__ target)
{
    int r = blockIdx.x;                // 0..959
    int t = r >> 6, b = r & 63;
    int tok = (t == 0) ? 0 : target[b * Tt + (t - 1)];
    reinterpret_cast<float4*>(&g_E[(size_t)r * Hh])[threadIdx.x] =
        reinterpret_cast<const float4*>(&emb[(size_t)tok * Hh])[threadIdx.x];
}

// ---------------- tf32 NT GEMM: C = A @ B^T (+bias) -------------------------
// A:[M,K] fp32 lda, B:[N,K] fp32 ldb. BM=64, BN=64, BK=16, 256 thr (8 warps 2x4).
// grid (N/64, M/64, KS). KS>1: writes slab ks at C + ks*slabStride (no bias).
// M,N multiples of 64; K/KS multiple of 16.
template <int KS>
__global__ __launch_bounds__(256) void gemm_tf32(
    const float* __restrict__ A, int lda,
    const float* __restrict__ Bm, int ldb,
    const float* __restrict__ bias,
    float* __restrict__ C, int ldc, size_t slabStride,
    int N, int K)
{
    __shared__ float As[64][18];
    __shared__ float Bs[64][18];
    const int tid   = threadIdx.x;
    const int nBase = blockIdx.x * 64;
    const int mBase = blockIdx.y * 64;
    const int ks    = blockIdx.z;
    const int kchunk = K / KS;
    const int k0s    = ks * kchunk;

    const int lrow = tid >> 2;
    const int lcol = (tid & 3) * 4;
    const int lane = tid & 31;
    const int warp = tid >> 5;
    const int wm   = warp & 1;        // 2 x 32 rows
    const int wn   = warp >> 1;       // 4 x 16 cols
    const int g    = lane >> 2;
    const int tt   = lane & 3;

    float acc[2][2][4];
#pragma unroll
    for (int i = 0; i < 2; i++)
#pragma unroll
        for (int j = 0; j < 2; j++)
#pragma unroll
            for (int e = 0; e < 4; e++) acc[i][j][e] = 0.f;

    for (int k0 = k0s; k0 < k0s + kchunk; k0 += 16) {
        float4 av = *reinterpret_cast<const float4*>(
            A + (size_t)(mBase + lrow) * lda + k0 + lcol);
        As[lrow][lcol+0] = cvt_tf32(av.x);
        As[lrow][lcol+1] = cvt_tf32(av.y);
        As[lrow][lcol+2] = cvt_tf32(av.z);
        As[lrow][lcol+3] = cvt_tf32(av.w);
        float4 bv = *reinterpret_cast<const float4*>(
            Bm + (size_t)(nBase + lrow) * ldb + k0 + lcol);
        Bs[lrow][lcol+0] = cvt_tf32(bv.x);
        Bs[lrow][lcol+1] = cvt_tf32(bv.y);
        Bs[lrow][lcol+2] = cvt_tf32(bv.z);
        Bs[lrow][lcol+3] = cvt_tf32(bv.w);
        __syncthreads();

#pragma unroll
        for (int kk = 0; kk < 16; kk += 8) {
            unsigned a[2][4];
#pragma unroll
            for (int ti = 0; ti < 2; ti++) {
                int r = wm*32 + ti*16;
                a[ti][0] = __float_as_uint(As[r + g    ][kk + tt    ]);
                a[ti][1] = __float_as_uint(As[r + g + 8][kk + tt    ]);
                a[ti][2] = __float_as_uint(As[r + g    ][kk + tt + 4]);
                a[ti][3] = __float_as_uint(As[r + g + 8][kk + tt + 4]);
            }
            unsigned bf[2][2];
#pragma unroll
            for (int nj = 0; nj < 2; nj++) {
                int rn = wn*16 + nj*8 + g;
                bf[nj][0] = __float_as_uint(Bs[rn][kk + tt    ]);
                bf[nj][1] = __float_as_uint(Bs[rn][kk + tt + 4]);
            }
#pragma unroll
            for (int ti = 0; ti < 2; ti++)
#pragma unroll
                for (int nj = 0; nj < 2; nj++)
                    mma_tf32_16808(acc[ti][nj][0], acc[ti][nj][1],
                                   acc[ti][nj][2], acc[ti][nj][3],
                                   a[ti][0], a[ti][1], a[ti][2], a[ti][3],
                                   bf[nj][0], bf[nj][1]);
        }
        __syncthreads();
    }

    float* Cs = C + (size_t)ks * slabStride;
#pragma unroll
    for (int ti = 0; ti < 2; ti++) {
        int m = mBase + wm*32 + ti*16 + g;
#pragma unroll
        for (int nj = 0; nj < 2; nj++) {
            int n = nBase + wn*16 + nj*8 + tt*2;
            float b0v = bias ? bias[n]   : 0.f;
            float b1v = bias ? bias[n+1] : 0.f;
            Cs[(size_t)m * ldc + n]       = acc[ti][nj][0] + b0v;
            Cs[(size_t)m * ldc + n + 1]   = acc[ti][nj][1] + b1v;
            Cs[(size_t)(m+8) * ldc + n]   = acc[ti][nj][2] + b0v;
            Cs[(size_t)(m+8) * ldc + n+1] = acc[ti][nj][3] + b1v;
        }
    }
}

// ---------------- bf16 tensor-core GEMM (logits) — unchanged, works --------
#define MMA_PAD 8
__global__ __launch_bounds__(128) void gemm_mma_bf16(
    const __nv_bfloat16* __restrict__ A, const __nv_bfloat16* __restrict__ Bm,
    const float* __restrict__ bias, float* __restrict__ C,
    int M, int N, int K, int ldc)
{
    __shared__ __nv_bfloat16 As[64][32 + MMA_PAD];
    __shared__ __nv_bfloat16 Bs[64][32 + MMA_PAD];
    const int tid   = threadIdx.x;
    const int lane  = tid & 31;
    const int warp  = tid >> 5;
    const int warpM = warp & 1;
    const int warpN = warp >> 1;
    const int mBase = blockIdx.x * 64;
    const int nBase = blockIdx.y * 64;

    float acc[2][4][4];
#pragma unroll
    for (int i = 0; i < 2; i++)
#pragma unroll
        for (int j = 0; j < 4; j++)
#pragma unroll
            for (int e = 0; e < 4; e++) acc[i][j][e] = 0.f;

    const int lr0 = tid >> 1;
    const int lq0 = (tid & 1) * 16;

    for (int k0 = 0; k0 < K; k0 += 32) {
        {
            const __nv_bfloat16* src = A + (size_t)(mBase + lr0) * K + k0 + lq0;
            uint4 v0 = *reinterpret_cast<const uint4*>(src);
            uint4 v1 = *reinterpret_cast<const uint4*>(src + 8);
            *reinterpret_cast<uint4*>(&As[lr0][lq0])     = v0;
            *reinterpret_cast<uint4*>(&As[lr0][lq0 + 8]) = v1;
        }
        {
            int n = nBase + lr0;
            uint4 v0 = make_uint4(0u,0u,0u,0u);
            uint4 v1 = make_uint4(0u,0u,0u,0u);
            if (n < N) {
                const __nv_bfloat16* src = Bm + (size_t)n * K + k0 + lq0;
                v0 = *reinterpret_cast<const uint4*>(src);
                v1 = *reinterpret_cast<const uint4*>(src + 8);
            }
            *reinterpret_cast<uint4*>(&Bs[lr0][lq0])     = v0;
            *reinterpret_cast<uint4*>(&Bs[lr0][lq0 + 8]) = v1;
        }
        __syncthreads();

#pragma unroll
        for (int k16 = 0; k16 < 32; k16 += 16) {
            unsigned afrag[2][4];
#pragma unroll
            for (int ti = 0; ti < 2; ti++) {
                int arow = warpM * 32 + ti * 16 + (lane & 15);
                int acol = k16 + (lane >> 4) * 8;
                ldsm_x4(afrag[ti][0], afrag[ti][1], afrag[ti][2], afrag[ti][3],
                        &As[arow][acol]);
            }
            unsigned bfrag[4][2];
#pragma unroll
            for (int tj = 0; tj < 2; tj++) {
                int grp  = lane >> 3;
                int brow = warpN * 32 + tj * 16 + (lane & 7) + ((grp >> 1) << 3);
                int bcol = k16 + ((grp & 1) << 3);
                unsigned q0, q1, q2, q3;
                ldsm_x4(q0, q1, q2, q3, &Bs[brow][bcol]);
                bfrag[tj*2][0]   = q0; bfrag[tj*2][1]   = q1;
                bfrag[tj*2+1][0] = q2; bfrag[tj*2+1][1] = q3;
            }
#pragma unroll
            for (int ti = 0; ti < 2; ti++)
#pragma unroll
                for (int nj = 0; nj < 4; nj++)
                    mma_bf16_16816(acc[ti][nj][0], acc[ti][nj][1],
                                   acc[ti][nj][2], acc[ti][nj][3],
                                   afrag[ti][0], afrag[ti][1],
                                   afrag[ti][2], afrag[ti][3],
                                   bfrag[nj][0], bfrag[nj][1]);
        }
        __syncthreads();
    }

#pragma unroll
    for (int ti = 0; ti < 2; ti++) {
        int m0 = mBase + warpM * 32 + ti * 16 + (lane >> 2);
#pragma unroll
        for (int nj = 0; nj < 4; nj++) {
            int n = nBase + warpN * 32 + nj * 8 + (lane & 3) * 2;
            if (n < N) {
                C[(size_t)m0 * ldc + n]     = acc[ti][nj][0] + bias[n];
                C[(size_t)(m0+8) * ldc + n] = acc[ti][nj][2] + bias[n];
            }
            if (n + 1 < N) {
                C[(size_t)m0 * ldc + n + 1]     = acc[ti][nj][1] + bias[n+1];
                C[(size_t)(m0+8) * ldc + n + 1] = acc[ti][nj][3] + bias[n+1];
            }
        }
    }
}

// ---------------- fused: q-reduce + scores + softmax + context --------------
// one block of 1024 threads per batch b
__global__ __launch_bounds__(1024) void attn_ctx_kernel(
    const float* __restrict__ enc, const float* __restrict__ Va,
    const float* __restrict__ ba, float* __restrict__ attn_out, int t)
{
    const int b   = blockIdx.x;
    const int tid = threadIdx.x;
    __shared__ float qsh[Hh];
    __shared__ float vsh[Hh];
    __shared__ float ssh[Ss];

    {
        float v = ba[tid];
#pragma unroll
        for (int p = 0; p < 4; p++)
            v += g_Phq[((size_t)p*Bb + b) * 4*Hh + tid];
        qsh[tid] = v;
        vsh[tid] = Va[tid];
    }
    __syncthreads();

    const int warp = tid >> 5, lane = tid & 31;
#pragma unroll
    for (int rep = 0; rep < 2; rep++) {
        int s = warp + rep * 32;
        const float* uk = &g_Uk[((size_t)b*Ss + s) * Hh];
        float acc = 0.f;
#pragma unroll 4
        for (int k = lane; k < Hh; k += 32)
            acc += tanh_fast(qsh[k] + uk[k]) * vsh[k];
#pragma unroll
        for (int o = 16; o > 0; o >>= 1)
            acc += __shfl_xor_sync(0xffffffffu, acc, o);
        if (lane == 0) ssh[s] = acc;
    }
    __syncthreads();

    if (tid < 32) {
        float x0 = ssh[tid], x1 = ssh[tid + 32];
        float m = fmaxf(x0, x1);
#pragma unroll
        for (int o = 16; o > 0; o >>= 1)
            m = fmaxf(m, __shfl_xor_sync(0xffffffffu, m, o));
        float e0 = expf(x0 - m), e1 = expf(x1 - m);
        float sum = e0 + e1;
#pragma unroll
        for (int o = 16; o > 0; o >>= 1)
            sum += __shfl_xor_sync(0xffffffffu, sum, o);
        float inv = 1.f / sum;
        float w0 = e0 * inv, w1 = e1 * inv;
        ssh[tid] = w0; ssh[tid + 32] = w1;
        size_t ob = (size_t)(b*Tt + t) * Ss;
        attn_out[ob + tid]      = w0;
        attn_out[ob + tid + 32] = w1;
    }
    __syncthreads();

    float acc = 0.f;
    const float* eb = enc + (size_t)(b*Ss) * Hh + tid;
#pragma unroll
    for (int s = 0; s < Ss; s++) acc = fmaf(ssh[s], eb[(size_t)s * Hh], acc);
    g_ctx[b*Hh + tid] = acc;
}

// ---------------- GRU combine --------------------------------------------
__global__ __launch_bounds__(256) void gru_combine_kernel(
    const float* __restrict__ b_hh, int t)
{
    const int idx = blockIdx.x * 256 + threadIdx.x;   // 0..65535
    const int b = idx >> 10;
    const int i = idx & 1023;

    // gi = giE (has b_ih) + ctx-part partials
    const float* ge = &g_giE[((size_t)t*Bb + b) * 3*Hh];
    float gir = ge[i], giz = ge[Hh + i], gin = ge[2*Hh + i];
#pragma unroll
    for (int p = 0; p < 4; p++) {
        const float* base = &g_Pgc[((size_t)p*Bb + b) * 3*Hh];
        gir += base[i]; giz += base[Hh + i]; gin += base[2*Hh + i];
    }
    // gh from hq partials (cols 1024..4095)
    float ghr = b_hh[i], ghz = b_hh[Hh + i], ghn = b_hh[2*Hh + i];
#pragma unroll
    for (int p = 0; p < 4; p++) {
        const float* base = &g_Phq[((size_t)p*Bb + b) * 4*Hh + Hh];
        ghr += base[i]; ghz += base[Hh + i]; ghn += base[2*Hh + i];
    }
    float r = 1.f / (1.f + expf(-(gir + ghr)));
    float z = 1.f / (1.f + expf(-(giz + ghz)));
    float n = tanhf(gin + r * ghn);
    float hprev = g_h[idx];
    float hnew  = (1.f - z) * n + z * hprev;
    g_h[idx] = hnew;
    g_Hall[(size_t)(b*Tt + t) * Hh + i] = hnew;
}

// ---------------- in-place log_softmax over V per row ----------------
__global__ __launch_bounds__(512) void log_softmax_kernel(float* __restrict__ out)
{
    const int row = blockIdx.x;
    float* x = out + (size_t)row * Vv;
    const int tid = threadIdx.x;

    float m = -INFINITY, s = 0.f;
    for (int v = tid; v < Vv; v += 512) {
        float xv = x[v];
        if (xv > m) { s = s * expf(m - xv) + 1.f; m = xv; }
        else        { s += expf(xv - m); }
    }
    __shared__ float sm[512], ss[512];
    sm[tid] = m; ss[tid] = s;
    __syncthreads();
    for (int stride = 256; stride > 0; stride >>= 1) {
        if (tid < stride) {
            float m2 = sm[tid + stride], s2 = ss[tid + stride];
            float M = fmaxf(sm[tid], m2);
            ss[tid] = ss[tid] * expf(sm[tid] - M) + s2 * expf(m2 - M);
            sm[tid] = M;
        }
        __syncthreads();
    }
    float lse = sm[0] + logf(ss[0]);
    for (int v = tid; v < Vv; v += 512) x[v] = x[v] - lse;
}

// ---------------- launch ----------------
extern "C" void kernel_launch(void* const* d_in, const int* in_sizes, int n_in,
                              void* d_out, int out_size)
{
    const float* enc   = (const float*)d_in[0];
    const float* ench  = (const float*)d_in[1];
    const int*   target= (const int*)  d_in[2];
    const float* emb   = (const float*)d_in[3];
    const float* Wa    = (const float*)d_in[4];
    const float* ba    = (const float*)d_in[5];
    const float* Ua    = (const float*)d_in[6];
    const float* bu    = (const float*)d_in[7];
    const float* Va    = (const float*)d_in[8];
    /* bv (d_in[9]): uniform shift before softmax — no effect */
    const float* W_ih  = (const float*)d_in[10];
    const float* W_hh  = (const float*)d_in[11];
    const float* b_ih  = (const float*)d_in[12];
    const float* b_hh  = (const float*)d_in[13];
    const float* Wout  = (const float*)d_in[14];
    const float* bout  = (const float*)d_in[15];

    float* out = (float*)d_out;
    float* lp  = out + LP_OFF;
    float* hT  = out + HT_OFF;
    float* at  = out + AT_OFF;

    float *pUk, *pH, *pCtx, *pHall, *pE, *pgiE, *pWhq, *pPhq, *pPgc;
    __nv_bfloat16 *pWoutB, *pHallB;
    cudaGetSymbolAddress((void**)&pUk,    g_Uk);
    cudaGetSymbolAddress((void**)&pH,     g_h);
    cudaGetSymbolAddress((void**)&pCtx,   g_ctx);
    cudaGetSymbolAddress((void**)&pHall,  g_Hall);
    cudaGetSymbolAddress((void**)&pE,     g_E);
    cudaGetSymbolAddress((void**)&pgiE,   g_giE);
    cudaGetSymbolAddress((void**)&pWhq,   g_Whq);
    cudaGetSymbolAddress((void**)&pPhq,   g_Phq);
    cudaGetSymbolAddress((void**)&pPgc,   g_Pgc);
    cudaGetSymbolAddress((void**)&pWoutB, g_WoutB);
    cudaGetSymbolAddress((void**)&pHallB, g_HallB);

    // prelude
    init_h_kernel<<<Bb, 1024>>>(ench);
    build_Whq_kernel<<<4096, 256>>>(Wa, W_hh);
    gather_E_kernel<<<Bb*Tt, 256>>>(emb, target);
    {
        int n4 = (Vv * Hh) / 4;
        f32_to_bf16_kernel<<<(n4 + 255)/256, 256>>>(Wout, pWoutB, n4);
    }
    // Uk = enc @ Ua^T + bu   (tf32)  M=4096 N=1024 K=1024
    gemm_tf32<1><<<dim3(Hh/64, (Bb*Ss)/64, 1), 256>>>(
        enc, Hh, Ua, Hh, bu, pUk, Hh, 0, Hh, Hh);
    // giE = E @ W_ih[:, :H]^T + b_ih  (tf32) M=960 N=3072 K=1024 (ldb=2048)
    gemm_tf32<1><<<dim3(3*Hh/64, (Bb*Tt)/64, 1), 256>>>(
        pE, Hh, W_ih, 2*Hh, b_ih, pgiE, 3*Hh, 0, 3*Hh, Hh);

    for (int t = 0; t < Tt; t++) {
        // [q | gh] = h @ Whq^T   (tf32 split-K)  M=64 N=4096 K=1024
        gemm_tf32<4><<<dim3(4*Hh/64, 1, 4), 256>>>(
            pH, Hh, pWhq, Hh, (const float*)nullptr,
            pPhq, 4*Hh, (size_t)Bb*4*Hh, 4*Hh, Hh);
        attn_ctx_kernel<<<Bb, 1024>>>(enc, Va, ba, at, t);
        // gi_ctx = ctx @ W_ih[:, H:]^T  (tf32 split-K) M=64 N=3072 K=1024
        gemm_tf32<4><<<dim3(3*Hh/64, 1, 4), 256>>>(
            pCtx, Hh, W_ih + Hh, 2*Hh, (const float*)nullptr,
            pPgc, 3*Hh, (size_t)Bb*3*Hh, 3*Hh, Hh);
        gru_combine_kernel<<<(Bb*Hh)/256, 256>>>(b_hh, t);
    }

    // Hall -> bf16
    {
        int n4 = (Bb * Tt * Hh) / 4;
        f32_to_bf16_kernel<<<(n4 + 255)/256, 256>>>(pHall, pHallB, n4);
    }
    // logits: Hall_bf16 @ WoutB^T + bout (bf16 HMMA)
    gemm_mma_bf16<<<dim3((Bb*Tt)/64, (Vv + 63)/64), 128>>>(
        pHallB, pWoutB, bout, lp, Bb*Tt, Vv, Hh, Vv);

    log_softmax_kernel<<<Bb*Tt, 512>>>(lp);
    copy_hT_kernel<<<Bb, 1024>>>(hT);
}